// round 9
// baseline (speedup 1.0000x reference)
#include <cuda_runtime.h>
#include <cuda_fp16.h>
#include <math.h>

#define Bb 128
#define Nn 128
#define Ee 300
#define Tt 255
#define CSZ 8
#define GPB 8

__device__ float g_buffer[Bb * Nn * 256];
__device__ float g_stack [Bb * Nn * 256];
__device__ float g_loss  [Bb];

__device__ __forceinline__ float sigf(float x) { return 1.0f / (1.0f + expf(-x)); }

__device__ __forceinline__ unsigned smem_u32(const void* p) {
    unsigned a;
    asm("{ .reg .u64 t; cvta.to.shared.u64 t, %1; cvt.u32.u64 %0, t; }" : "=r"(a) : "l"(p));
    return a;
}
__device__ __forceinline__ void fence_cluster() {
    asm volatile("fence.acq_rel.cluster;" ::: "memory");
}
__device__ __forceinline__ void arrive_peer_rel(unsigned la, int p) {
    asm volatile("{ .reg .b32 ra; mapa.shared::cluster.u32 ra, %0, %1;"
                 " mbarrier.arrive.release.cluster.shared::cluster.b64 _, [ra]; }"
                 :: "r"(la), "r"(p) : "memory");
}
__device__ __forceinline__ void arrive_local(unsigned la) {
    asm volatile("mbarrier.arrive.shared.b64 _, [%0];" :: "r"(la) : "memory");
}
__device__ __forceinline__ void wait_parity_cluster(unsigned a, unsigned par) {
    asm volatile("{ .reg .pred P;\n"
                 "W_%=:\n"
                 " mbarrier.try_wait.parity.acquire.cluster.shared::cta.b64 P, [%0], %1, 0x989680;\n"
                 " @P bra D_%=;\n"
                 " bra W_%=;\n"
                 "D_%=:\n}"
                 :: "r"(a), "r"(par) : "memory");
}
__device__ __forceinline__ void st_remote_b64(unsigned la, int p, float x, float y) {
    unsigned long long v = ((unsigned long long)__float_as_uint(y) << 32)
                         | (unsigned long long)__float_as_uint(x);
    asm volatile("{ .reg .b32 ra; mapa.shared::cluster.u32 ra, %0, %1;"
                 " st.shared::cluster.b64 [ra], %2; }"
                 :: "r"(la), "r"(p), "l"(v) : "memory");
}

// ---------------------------------------------------------------------------
// Kernel 1: buffer[b,n,:] = embed_table[tokens[b,n]] @ W_proj
// ---------------------------------------------------------------------------
__global__ void __launch_bounds__(256) embed_kernel(
    const int*   __restrict__ tokens,
    const float* __restrict__ embed_table,
    const float* __restrict__ W_proj)
{
    __shared__ float se[16 * Ee];
    __shared__ int   stok[16];
    const int blk = blockIdx.x;
    const int tid = threadIdx.x;

    if (tid < 16) stok[tid] = tokens[blk * 16 + tid];
    __syncthreads();
    for (int idx = tid; idx < 16 * Ee; idx += 256) {
        int j = idx / Ee, e = idx - j * Ee;
        se[idx] = embed_table[(size_t)stok[j] * Ee + e];
    }
    __syncthreads();

    const int col = tid;
    float acc[16];
#pragma unroll
    for (int j = 0; j < 16; j++) acc[j] = 0.0f;
    for (int e = 0; e < Ee; e++) {
        float w = W_proj[e * 256 + col];
#pragma unroll
        for (int j = 0; j < 16; j++) acc[j] += se[j * Ee + e] * w;
    }
#pragma unroll
    for (int j = 0; j < 16; j++)
        g_buffer[(size_t)(blk * 16 + j) * 256 + col] = acc[j];
}

// ---------------------------------------------------------------------------
// Kernel 2: clustered scan; conditional sbar, consumer-side hbar, lazy loss
// ---------------------------------------------------------------------------
struct __align__(16) Smem {
    float wK[2 * 128 * 64];         // W_buf, W_s1 fp32 [k][64]
    float h_s[2][GPB][128];
    float bt[GPB][256];
    float s1v[GPB][256];
    float s2v[GPB][256];
    float red_s[2][GPB][256];       // double-buffered by reduce-parity
    float pt[2560];
    float c_s[GPB][16];
    float bias_lat[64];
    float bias_red[80];
    float wtrans[256];
    float btr[2];
    int   fin_ptr[GPB];
    unsigned long long mbar[2];     // [0]=hbar, [1]=sbar (count 256 each)
    __half wS2[64 * 130];
    __half wLat[64 * 130];
    __half wT[80 * 386];
    unsigned trbits[GPB][8];
    unsigned char sch_wp[Tt][GPB];
    unsigned char sch_bt[Tt + 1][GPB];
    signed char   sch_rf[Tt][GPB];
};

__global__ void __launch_bounds__(256, 1) __cluster_dims__(CSZ, 1, 1)
spinn_seq(
    const int*   __restrict__ transitions,
    const float* __restrict__ W_buf,  const float* __restrict__ W_s1,
    const float* __restrict__ W_s2,   const float* __restrict__ W_lat,
    const float* __restrict__ b_lat,
    const float* __restrict__ W_trans,const float* __restrict__ b_trans,
    const float* __restrict__ W_left, const float* __restrict__ W_right,
    const float* __restrict__ W_track,const float* __restrict__ b_reduce,
    float* __restrict__ out_final)
{
    extern __shared__ char smraw[];
    Smem* sm = (Smem*)smraw;
    const int tid = threadIdx.x;
    const int r   = blockIdx.x & (CSZ - 1);
    const int b0  = blockIdx.x & ~(CSZ - 1);

    float*       stck = g_stack  + (size_t)b0 * Nn * 256;
    const float* buf  = g_buffer + (size_t)b0 * Nn * 256;

    // ---------------- init ----------------
    for (int idx = tid; idx < 2 * 128 * 64; idx += 256) {
        int k = idx >> 6, c = idx & 63;
        int G = ((c >> 4) << 7) + (r << 4) + (c & 15);
        sm->wK[idx] = (k < 128) ? W_buf[k * 512 + G] : W_s1[(k - 128) * 512 + G];
    }
    for (int idx = tid; idx < 64 * 128; idx += 256) {
        int c = idx >> 7, k = idx & 127;
        int G = ((c >> 4) << 7) + (r << 4) + (c & 15);
        sm->wS2 [c * 130 + k] = __float2half(W_s2 [k * 512 + G]);
        sm->wLat[c * 130 + k] = __float2half(W_lat[k * 512 + G]);
    }
    for (int idx = tid; idx < 80 * 384; idx += 256) {
        int c = idx / 384, k = idx - c * 384;
        int G = ((c >> 4) << 7) + (r << 4) + (c & 15);
        float w = (k < 128) ? W_left[k * 640 + G]
                : (k < 256) ? W_right[(k - 128) * 640 + G]
                            : W_track[(k - 256) * 640 + G];
        sm->wT[c * 386 + k] = __float2half(w);
    }
    if (tid < 64) sm->bias_lat[tid] = b_lat[((tid >> 4) << 7) + (r << 4) + (tid & 15)];
    if (tid < 80) sm->bias_red[tid] = b_reduce[((tid >> 4) << 7) + (r << 4) + (tid & 15)];
    sm->wtrans[tid] = W_trans[tid];
    if (tid < 2) sm->btr[tid] = b_trans[tid];
    if (tid < 64) {
        int g = tid >> 3, w = tid & 7;
        unsigned bits = 0;
        for (int i = 0; i < 32; i++) {
            int tt = w * 32 + i;
            if (tt < Tt) bits |= (unsigned)(transitions[(b0 + g) * Tt + tt] & 1) << i;
        }
        sm->trbits[g][w] = bits;
    }
    for (int i = tid; i < 2 * GPB * 128; i += 256) ((float*)sm->h_s)[i] = 0.f;
    for (int i = tid; i < GPB * 16;  i += 256) ((float*)sm->c_s)[i] = 0.f;
    for (int i = tid; i < GPB * 256; i += 256) {
        ((float*)sm->s1v)[i] = 0.f;
        ((float*)sm->s2v)[i] = 0.f;
    }
    for (int i = tid; i < 2 * GPB * 256; i += 256) ((float*)sm->red_s)[i] = 0.f;
    for (int i = tid; i < GPB * 64; i += 256) {
        int b = i >> 6, q = (i & 63) * 4;
        *(float4*)&sm->bt[b][q] = *(const float4*)&buf[((size_t)b * Nn) * 256 + q];
    }
    if (tid == 0) {
        unsigned mb = smem_u32(&sm->mbar[0]);
        asm volatile("mbarrier.init.shared.b64 [%0], %1;" :: "r"(mb),   "r"(256) : "memory");
        asm volatile("mbarrier.init.shared.b64 [%0], %1;" :: "r"(mb+8), "r"(256) : "memory");
    }
    __syncthreads();

    if (tid < GPB) {
        const int g = tid;
        int p = 0, bp = 0;
        for (int t = 0; t < Tt; t++) {
            int trv = (sm->trbits[g][t >> 5] >> (t & 31)) & 1;
            int bi = (bp < Nn - 1) ? bp : (Nn - 1);
            sm->sch_bt[t][g] = (unsigned char)bi;
            int wp = trv ? ((p - 2 >= 0) ? p - 2 : 0) : p;
            if (wp > Nn - 1) wp = Nn - 1;
            sm->sch_wp[t][g] = (unsigned char)wp;
            sm->sch_rf[t][g] = (signed char)((trv && p >= 3) ? (p - 3) : -1);
            p  += trv ? -1 : 1;
            bp += trv ? 0 : 1;
        }
        sm->sch_bt[Tt][g] = sm->sch_bt[Tt - 1][g];
        int fin = (p - 1 >= 0) ? p - 1 : 0;
        sm->fin_ptr[g] = (fin > Nn - 1) ? Nn - 1 : fin;
    }
    __syncthreads();
    asm volatile("barrier.cluster.arrive.aligned;" ::: "memory");
    asm volatile("barrier.cluster.wait.aligned;"   ::: "memory");

    const unsigned hbar    = smem_u32(&sm->mbar[0]);
    const unsigned sbar    = hbar + 8;
    const unsigned hsbase  = smem_u32(&sm->h_s[0][0][0]);
    const unsigned redbase = smem_u32(&sm->red_s[0][0][0]);

    const int pb = tid >> 5;
    const int pd = (tid & 31) * 8;
    // publish mapping (tid < 224): peer + chunk
    const int pid  = tid >> 5;                         // 0..6 for tid<224
    const int peer = pid + (pid >= r ? 1 : 0);
    const int chnk = tid & 31;

    const float4 z4 = make_float4(0.f, 0.f, 0.f, 0.f);
    float4 rfa = z4, rfb = z4;
    float4 bna = z4, bnb = z4;
    float loss_reg = 0.f;
    int sp = 0;                    // reduce-step counter (sbar phase)
    int prevAny = 0;

    for (int t = 0; t < Tt; t++) {
        const int w5 = t >> 5, b5 = t & 31;
        const int rb = t & 1, wbuf = 1 - rb;

        unsigned anyr = 0;
#pragma unroll
        for (int g = 0; g < GPB; g++) anyr |= (sm->trbits[g][w5] >> b5) & 1u;

        // ---- P0: prefetch; conditional sbar wait + reduce-rename ----
        {
            int nbt = sm->sch_bt[t + 1][pb];
            const float* bsrc = &buf[((size_t)pb * Nn + nbt) * 256 + pd];
            bna = __ldg((const float4*)bsrc);
            bnb = __ldg((const float4*)(bsrc + 4));
            int rfi = sm->sch_rf[t][pb];
            if (rfi >= 0) {
                const float* rsrc = &stck[((size_t)pb * Nn + rfi) * 256 + pd];
                rfa = __ldcg((const float4*)rsrc);
                rfb = __ldcg((const float4*)(rsrc + 4));
            } else { rfa = z4; rfb = z4; }
        }
        if (prevAny) {
            wait_parity_cluster(sbar, sp & 1);
            const int slot = sp & 1;
            if ((sm->trbits[pb][(t - 1) >> 5] >> ((t - 1) & 31)) & 1) {
                float4 r0 = *(const float4*)&sm->red_s[slot][pb][pd];
                float4 r1 = *(const float4*)&sm->red_s[slot][pb][pd + 4];
                *(float4*)&sm->s1v[pb][pd]     = r0;
                *(float4*)&sm->s1v[pb][pd + 4] = r1;
                *(float4*)&sm->s2v[pb][pd]     = rfa;
                *(float4*)&sm->s2v[pb][pd + 4] = rfb;
            }
            sp++;
        }
        __syncthreads();   // SYNC0

        // ---- P1: tracker GEMM (kc=3 warps wait hbar(t-1) lazily) + lazy loss ----
        {
            const int col = tid & 63, kc = tid >> 6;
            float acc[GPB];
#pragma unroll
            for (int b = 0; b < GPB; b++) acc[b] = 0.f;
            if (kc < 2) {
                const float* xb = (kc == 0) ? &sm->bt[0][0] : &sm->s1v[0][0];
                const float* wr = &sm->wK[kc * 128 * 64 + col];
                for (int kl = 0; kl < 128; kl += 4) {
                    float w0 = wr[(kl + 0) * 64], w1 = wr[(kl + 1) * 64];
                    float w2 = wr[(kl + 2) * 64], w3 = wr[(kl + 3) * 64];
#pragma unroll
                    for (int b = 0; b < GPB; b++) {
                        float4 x = *(const float4*)&xb[b * 256 + kl];
                        acc[b] += x.x * w0 + x.y * w1 + x.z * w2 + x.w * w3;
                    }
                }
            } else {
                if (kc == 3 && t > 0) wait_parity_cluster(hbar, (t - 1) & 1);
                const float* xb = (kc == 2) ? &sm->s2v[0][0] : &sm->h_s[rb][0][0];
                const int xs = (kc == 3) ? 128 : 256;
                const __half* wl = (kc == 2) ? &sm->wS2[col * 130] : &sm->wLat[col * 130];
                for (int kl = 0; kl < 128; kl += 4) {
                    float2 wf0 = __half22float2(*(const __half2*)&wl[kl]);
                    float2 wf1 = __half22float2(*(const __half2*)&wl[kl + 2]);
#pragma unroll
                    for (int b = 0; b < GPB; b++) {
                        float4 x = *(const float4*)&xb[b * xs + kl];
                        acc[b] += x.x * wf0.x + x.y * wf0.y + x.z * wf1.x + x.w * wf1.y;
                    }
                }
            }
            *(float4*)&sm->pt[kc * 512 + col * 8]     = make_float4(acc[0], acc[1], acc[2], acc[3]);
            *(float4*)&sm->pt[kc * 512 + col * 8 + 4] = make_float4(acc[4], acc[5], acc[6], acc[7]);
        }
        // deferred loss for step t-1 (h(t-1) is in h_s[rb], already waited by kc=3)
        if (t > 0 && tid >= 224) {
            const int l = tid - 224;
            float p0 = 0.f, p1 = 0.f;
#pragma unroll
            for (int m = 0; m < 4; m++) {
                int j = l + 32 * m;
                float h = sm->h_s[rb][r][j];
                p0 += h * sm->wtrans[2 * j];
                p1 += h * sm->wtrans[2 * j + 1];
            }
#pragma unroll
            for (int off = 16; off > 0; off >>= 1) {
                p0 += __shfl_xor_sync(0xffffffffu, p0, off);
                p1 += __shfl_xor_sync(0xffffffffu, p1, off);
            }
            if (l == 0) {
                float l0 = p0 + sm->btr[0], l1 = p1 + sm->btr[1];
                float m = fmaxf(l0, l1);
                float lse = m + logf(expf(l0 - m) + expf(l1 - m));
                int trp = (sm->trbits[r][(t - 1) >> 5] >> ((t - 1) & 31)) & 1;
                loss_reg += lse - ((trp == 0) ? l0 : l1);
            }
        }
        __syncthreads();   // SYNC1

        // ---- P2: cell update (local h_s write) ----
        if (tid < 128) {
            const int jj = tid >> 3, b = tid & 7;
            float ga[4];
#pragma unroll
            for (int g = 0; g < 4; g++) {
                int c = g * 16 + jj;
                float v = sm->pt[c * 8 + b] + sm->pt[512 + c * 8 + b]
                        + sm->pt[1024 + c * 8 + b] + sm->pt[1536 + c * 8 + b];
                if (t > 0) v += sm->bias_lat[c];
                ga[g] = v;
            }
            float cn = sigf(ga[2]) * sm->c_s[b][jj] + sigf(ga[1]) * tanhf(ga[0]);
            float hn = sigf(ga[3]) * tanhf(cn);
            sm->c_s[b][jj] = cn;
            sm->h_s[wbuf][b][(r << 4) + jj] = hn;
        }
        __syncthreads();   // SYNC2

        // ---- P3: h publish (b64 x2 per thread) + per-thread release arrive;
        //          then tree L/R (overlaps peers' latency) ----
        if (tid < 224) {
#pragma unroll
            for (int rr = 0; rr < 2; rr++) {
                int u = chnk + rr * 32;              // 0..63
                int b = u >> 3, o = (u & 7) * 2;
                float2 hv = *(const float2*)&sm->h_s[wbuf][b][(r << 4) + o];
                unsigned la = hsbase + (unsigned)(((wbuf * GPB + b) * 128 + (r << 4) + o) * 4);
                st_remote_b64(la, peer, hv.x, hv.y);
            }
            arrive_peer_rel(hbar, peer);
        } else {
            arrive_local(hbar);
        }
        if (anyr && tid < 160) {
            const int kc = tid / 80, c = tid - kc * 80;   // 0=left(s2), 1=right(s1)
            const float* xb = (kc == 0) ? &sm->s2v[0][0] : &sm->s1v[0][0];
            const __half* wr = &sm->wT[c * 386 + kc * 128];
            float acc[GPB];
#pragma unroll
            for (int b = 0; b < GPB; b++) acc[b] = 0.f;
            for (int kl = 0; kl < 128; kl += 4) {
                float2 wf0 = __half22float2(*(const __half2*)&wr[kl]);
                float2 wf1 = __half22float2(*(const __half2*)&wr[kl + 2]);
#pragma unroll
                for (int b = 0; b < GPB; b++) {
                    float4 x = *(const float4*)&xb[b * 256 + kl];
                    acc[b] += x.x * wf0.x + x.y * wf0.y + x.z * wf1.x + x.w * wf1.y;
                }
            }
            *(float4*)&sm->pt[kc * 640 + c * 8]     = make_float4(acc[0], acc[1], acc[2], acc[3]);
            *(float4*)&sm->pt[kc * 640 + c * 8 + 4] = make_float4(acc[4], acc[5], acc[6], acc[7]);
        }

        // ---- P4: track slice (waits hbar(t) — hidden behind L/R) ----
        if (anyr && tid < 160) {
            wait_parity_cluster(hbar, t & 1);
            const int half = tid / 80, c = tid - half * 80;
            const float* xb = &sm->h_s[wbuf][0][0];
            const __half* wr = &sm->wT[c * 386 + 256 + half * 64];
            const int k0 = half * 64;
            float acc[GPB];
#pragma unroll
            for (int b = 0; b < GPB; b++) acc[b] = 0.f;
            for (int kl = 0; kl < 64; kl += 4) {
                float2 wf0 = __half22float2(*(const __half2*)&wr[kl]);
                float2 wf1 = __half22float2(*(const __half2*)&wr[kl + 2]);
#pragma unroll
                for (int b = 0; b < GPB; b++) {
                    float4 x = *(const float4*)&xb[b * 128 + k0 + kl];
                    acc[b] += x.x * wf0.x + x.y * wf0.y + x.z * wf1.x + x.w * wf1.y;
                }
            }
            *(float4*)&sm->pt[1280 + half * 640 + c * 8]     = make_float4(acc[0], acc[1], acc[2], acc[3]);
            *(float4*)&sm->pt[1280 + half * 640 + c * 8 + 4] = make_float4(acc[4], acc[5], acc[6], acc[7]);
        }
        __syncthreads();   // SYNC3

        // ---- P5: compose -> red_s[slot] local + stack stcg || shift stack write ----
        const int slotW = sp & 1;   // publish slot for this reduce step
        if (tid < 128) {
            const int jj = tid >> 3, b = tid & 7;
            if ((sm->trbits[b][w5] >> b5) & 1) {
                const int j = (r << 4) + jj;
                float gg[5];
#pragma unroll
                for (int g = 0; g < 5; g++) {
                    int c = g * 16 + jj;
                    gg[g] = sm->pt[c * 8 + b] + sm->pt[640 + c * 8 + b]
                          + sm->pt[1280 + c * 8 + b] + sm->pt[1920 + c * 8 + b]
                          + sm->bias_red[c];
                }
                float cn = tanhf(gg[0]) * sigf(gg[1])
                         + sigf(gg[2]) * sm->s2v[b][128 + j]
                         + sigf(gg[3]) * sm->s1v[b][128 + j];
                float v1 = cn;
                float v0 = sigf(gg[4]) * tanhf(cn);
                const int wp = sm->sch_wp[t][b];
                __stcg(&stck[((size_t)b * Nn + wp) * 256 + j], v0);
                __stcg(&stck[((size_t)b * Nn + wp) * 256 + 128 + j], v1);
                sm->red_s[slotW][b][j]       = v0;
                sm->red_s[slotW][b][128 + j] = v1;
            }
        } else if (tid < 192) {
            const int u = tid - 128;
            const int b = u >> 3, q = (u & 7) * 4;
            if (((sm->trbits[b][w5] >> b5) & 1) == 0) {
                const int wp = sm->sch_wp[t][b];
                __stcg((float4*)&stck[((size_t)b * Nn + wp) * 256 + r * 32 + q],
                       *(const float4*)&sm->bt[b][r * 32 + q]);
            }
        }
        __syncthreads();   // SYNC4

        // ---- P6: red publish + sbar arrive (reduce only) + shift rename ----
        if (anyr) {
            if (tid < 224) {
#pragma unroll
                for (int rr = 0; rr < 4; rr++) {
                    int u = chnk + rr * 32;                  // 0..127
                    int half = u >> 6, b = (u >> 3) & 7, o = (u & 7) * 2;
                    float2 rv = *(const float2*)&sm->red_s[slotW][b][half * 128 + (r << 4) + o];
                    unsigned la = redbase + (unsigned)(((slotW * GPB + b) * 256
                                   + half * 128 + (r << 4) + o) * 4);
                    st_remote_b64(la, peer, rv.x, rv.y);
                }
                arrive_peer_rel(sbar, peer);
            } else {
                arrive_local(sbar);
            }
        }
        if (((sm->trbits[pb][w5] >> b5) & 1) == 0) {
            float4 s1a = *(const float4*)&sm->s1v[pb][pd];
            float4 s1b = *(const float4*)&sm->s1v[pb][pd + 4];
            float4 bta = *(const float4*)&sm->bt[pb][pd];
            float4 btb = *(const float4*)&sm->bt[pb][pd + 4];
            *(float4*)&sm->s2v[pb][pd]     = s1a;
            *(float4*)&sm->s2v[pb][pd + 4] = s1b;
            *(float4*)&sm->s1v[pb][pd]     = bta;
            *(float4*)&sm->s1v[pb][pd + 4] = btb;
            *(float4*)&sm->bt[pb][pd]      = bna;
            *(float4*)&sm->bt[pb][pd + 4]  = bnb;
        }
        prevAny = anyr;
    }

    fence_cluster();
    asm volatile("barrier.cluster.arrive.aligned;" ::: "memory");
    asm volatile("barrier.cluster.wait.aligned;"   ::: "memory");

    // final step's loss (h(Tt-1) is in h_s[1 - ((Tt-1)&1)])
    if (tid >= 224) {
        const int l = tid - 224;
        const int wb_last = 1 - ((Tt - 1) & 1);
        float p0 = 0.f, p1 = 0.f;
#pragma unroll
        for (int m = 0; m < 4; m++) {
            int j = l + 32 * m;
            float h = sm->h_s[wb_last][r][j];
            p0 += h * sm->wtrans[2 * j];
            p1 += h * sm->wtrans[2 * j + 1];
        }
#pragma unroll
        for (int off = 16; off > 0; off >>= 1) {
            p0 += __shfl_xor_sync(0xffffffffu, p0, off);
            p1 += __shfl_xor_sync(0xffffffffu, p1, off);
        }
        if (l == 0) {
            float l0 = p0 + sm->btr[0], l1 = p1 + sm->btr[1];
            float m = fmaxf(l0, l1);
            float lse = m + logf(expf(l0 - m) + expf(l1 - m));
            int trp = (sm->trbits[r][(Tt - 1) >> 5] >> ((Tt - 1) & 31)) & 1;
            loss_reg += lse - ((trp == 0) ? l0 : l1);
            g_loss[b0 + r] = loss_reg;
        }
    }

    if (tid < 64) {
        int fin = sm->fin_ptr[r];
        float4 v = __ldcg((const float4*)&stck[((size_t)r * Nn + fin) * 256 + tid * 4]);
        *(float4*)&out_final[(size_t)(b0 + r) * 256 + tid * 4] = v;
    }
}

// ---------------------------------------------------------------------------
// Kernel 3: loss reduction
// ---------------------------------------------------------------------------
__global__ void loss_kernel(float* __restrict__ out, int loss_idx)
{
    __shared__ float sl[128];
    int tid = threadIdx.x;
    sl[tid] = g_loss[tid];
    __syncthreads();
    for (int off = 64; off > 0; off >>= 1) {
        if (tid < off) sl[tid] += sl[tid + off];
        __syncthreads();
    }
    if (tid == 0) out[loss_idx] = sl[0] / (float)(Tt * Bb);
}

// ---------------------------------------------------------------------------
extern "C" void kernel_launch(void* const* d_in, const int* in_sizes, int n_in,
                              void* d_out, int out_size)
{
    const int*   tokens      = (const int*)  d_in[0];
    const int*   transitions = (const int*)  d_in[1];
    const float* embed_table = (const float*)d_in[2];
    const float* W_proj      = (const float*)d_in[3];
    const float* W_buf       = (const float*)d_in[4];
    const float* W_s1        = (const float*)d_in[5];
    const float* W_s2        = (const float*)d_in[6];
    const float* W_lat       = (const float*)d_in[7];
    const float* b_lat       = (const float*)d_in[8];
    const float* W_trans     = (const float*)d_in[9];
    const float* b_trans     = (const float*)d_in[10];
    const float* W_left      = (const float*)d_in[11];
    const float* W_right     = (const float*)d_in[12];
    const float* W_track     = (const float*)d_in[13];
    const float* b_reduce    = (const float*)d_in[14];
    float* out = (float*)d_out;

    static bool attr_done = false;
    if (!attr_done) {
        cudaFuncSetAttribute(spinn_seq,
                             cudaFuncAttributeMaxDynamicSharedMemorySize,
                             (int)sizeof(Smem));
        attr_done = true;
    }

    embed_kernel<<<(Bb * Nn) / 16, 256>>>(tokens, embed_table, W_proj);
    spinn_seq<<<Bb, 256, sizeof(Smem)>>>(transitions,
                                         W_buf, W_s1, W_s2, W_lat, b_lat,
                                         W_trans, b_trans,
                                         W_left, W_right, W_track, b_reduce,
                                         out);
    loss_kernel<<<1, 128>>>(out, out_size - 1);
}

// round 10
// speedup vs baseline: 1.1530x; 1.1530x over previous
#include <cuda_runtime.h>
#include <cuda_fp16.h>
#include <math.h>

#define Bb 128
#define Nn 128
#define Ee 300
#define Tt 255
#define CSZ 8
#define GPB 8
#define NT 512

__device__ float g_buffer[Bb * Nn * 256];
__device__ float g_stack [Bb * Nn * 256];
__device__ float g_loss  [Bb];

__device__ __forceinline__ float sigf(float x) { return 1.0f / (1.0f + expf(-x)); }

__device__ __forceinline__ unsigned smem_u32(const void* p) {
    unsigned a;
    asm("{ .reg .u64 t; cvta.to.shared.u64 t, %1; cvt.u32.u64 %0, t; }" : "=r"(a) : "l"(p));
    return a;
}
__device__ __forceinline__ void fence_cluster() {
    asm volatile("fence.acq_rel.cluster;" ::: "memory");
}
__device__ __forceinline__ void arrive_peer_rel(unsigned la, int p) {
    asm volatile("{ .reg .b32 ra; mapa.shared::cluster.u32 ra, %0, %1;"
                 " mbarrier.arrive.release.cluster.shared::cluster.b64 _, [ra]; }"
                 :: "r"(la), "r"(p) : "memory");
}
__device__ __forceinline__ void wait_parity_cluster(unsigned a, unsigned par) {
    asm volatile("{ .reg .pred P;\n"
                 "W_%=:\n"
                 " mbarrier.try_wait.parity.acquire.cluster.shared::cta.b64 P, [%0], %1, 0x989680;\n"
                 " @P bra D_%=;\n"
                 " bra W_%=;\n"
                 "D_%=:\n}"
                 :: "r"(a), "r"(par) : "memory");
}
__device__ __forceinline__ void st_remote_b64(unsigned la, int p, float x, float y) {
    unsigned long long v = ((unsigned long long)__float_as_uint(y) << 32)
                         | (unsigned long long)__float_as_uint(x);
    asm volatile("{ .reg .b32 ra; mapa.shared::cluster.u32 ra, %0, %1;"
                 " st.shared::cluster.b64 [ra], %2; }"
                 :: "r"(la), "r"(p), "l"(v) : "memory");
}

// ---------------------------------------------------------------------------
// Kernel 1: buffer[b,n,:] = embed_table[tokens[b,n]] @ W_proj
// ---------------------------------------------------------------------------
__global__ void __launch_bounds__(256) embed_kernel(
    const int*   __restrict__ tokens,
    const float* __restrict__ embed_table,
    const float* __restrict__ W_proj)
{
    __shared__ float se[16 * Ee];
    __shared__ int   stok[16];
    const int blk = blockIdx.x;
    const int tid = threadIdx.x;

    if (tid < 16) stok[tid] = tokens[blk * 16 + tid];
    __syncthreads();
    for (int idx = tid; idx < 16 * Ee; idx += 256) {
        int j = idx / Ee, e = idx - j * Ee;
        se[idx] = embed_table[(size_t)stok[j] * Ee + e];
    }
    __syncthreads();

    const int col = tid;
    float acc[16];
#pragma unroll
    for (int j = 0; j < 16; j++) acc[j] = 0.0f;
    for (int e = 0; e < Ee; e++) {
        float w = W_proj[e * 256 + col];
#pragma unroll
        for (int j = 0; j < 16; j++) acc[j] += se[j * Ee + e] * w;
    }
#pragma unroll
    for (int j = 0; j < 16; j++)
        g_buffer[(size_t)(blk * 16 + j) * 256 + col] = acc[j];
}

// ---------------------------------------------------------------------------
// Kernel 2: clustered scan, 512 threads/CTA, k-split phases, balanced tree
// ---------------------------------------------------------------------------
struct __align__(16) Smem {
    float h_s[2][GPB][128];
    float bt[GPB][256];
    float s1v[GPB][256];
    float s2v[GPB][256];
    float red_s[2][GPB][256];
    float pt[4096];                 // tracker 8*64*8 | tree 6*80*8
    float c_s[GPB][16];
    float bias_lat[64];
    float bias_red[80];
    float wtrans[256];
    float btr[2];
    int   fin_ptr[GPB];
    unsigned long long mbar[2];     // [0]=hbar, [1]=sbar, count 224
    __half wTrk[256 * 130];         // [kc*64+c][k]  kc: buf,s1,s2,lat
    __half wT[80 * 386];            // [c][m*128+k]  m: left,right,track
    unsigned trbits[GPB][8];
    unsigned char sch_wp[Tt][GPB];
    unsigned char sch_bt[Tt + 1][GPB];
    signed char   sch_rf[Tt][GPB];
};

__global__ void __launch_bounds__(NT, 1) __cluster_dims__(CSZ, 1, 1)
spinn_seq(
    const int*   __restrict__ transitions,
    const float* __restrict__ W_buf,  const float* __restrict__ W_s1,
    const float* __restrict__ W_s2,   const float* __restrict__ W_lat,
    const float* __restrict__ b_lat,
    const float* __restrict__ W_trans,const float* __restrict__ b_trans,
    const float* __restrict__ W_left, const float* __restrict__ W_right,
    const float* __restrict__ W_track,const float* __restrict__ b_reduce,
    float* __restrict__ out_final)
{
    extern __shared__ char smraw[];
    Smem* sm = (Smem*)smraw;
    const int tid = threadIdx.x;
    const int r   = blockIdx.x & (CSZ - 1);
    const int b0  = blockIdx.x & ~(CSZ - 1);

    float*       stck = g_stack  + (size_t)b0 * Nn * 256;
    const float* buf  = g_buffer + (size_t)b0 * Nn * 256;

    // ---------------- init ----------------
    for (int idx = tid; idx < 256 * 128; idx += NT) {
        int row = idx >> 7, k = idx & 127;    // row = kc*64 + c
        int kc = row >> 6, c = row & 63;
        int G = ((c >> 4) << 7) + (r << 4) + (c & 15);
        const float* W = (kc == 0) ? W_buf : (kc == 1) ? W_s1
                       : (kc == 2) ? W_s2 : W_lat;
        sm->wTrk[row * 130 + k] = __float2half(W[k * 512 + G]);
    }
    for (int idx = tid; idx < 80 * 384; idx += NT) {
        int c = idx / 384, k = idx - c * 384;
        int G = ((c >> 4) << 7) + (r << 4) + (c & 15);
        float w = (k < 128) ? W_left[k * 640 + G]
                : (k < 256) ? W_right[(k - 128) * 640 + G]
                            : W_track[(k - 256) * 640 + G];
        sm->wT[c * 386 + k] = __float2half(w);
    }
    if (tid < 64) sm->bias_lat[tid] = b_lat[((tid >> 4) << 7) + (r << 4) + (tid & 15)];
    if (tid < 80) sm->bias_red[tid] = b_reduce[((tid >> 4) << 7) + (r << 4) + (tid & 15)];
    if (tid < 256) sm->wtrans[tid] = W_trans[tid];
    if (tid < 2) sm->btr[tid] = b_trans[tid];
    if (tid < 64) {
        int g = tid >> 3, w = tid & 7;
        unsigned bits = 0;
        for (int i = 0; i < 32; i++) {
            int tt = w * 32 + i;
            if (tt < Tt) bits |= (unsigned)(transitions[(b0 + g) * Tt + tt] & 1) << i;
        }
        sm->trbits[g][w] = bits;
    }
    for (int i = tid; i < 2 * GPB * 128; i += NT) ((float*)sm->h_s)[i] = 0.f;
    for (int i = tid; i < GPB * 16;  i += NT) ((float*)sm->c_s)[i] = 0.f;
    for (int i = tid; i < GPB * 256; i += NT) {
        ((float*)sm->s1v)[i] = 0.f;
        ((float*)sm->s2v)[i] = 0.f;
    }
    for (int i = tid; i < 2 * GPB * 256; i += NT) ((float*)sm->red_s)[i] = 0.f;
    for (int i = tid; i < GPB * 64; i += NT) {
        int b = i >> 6, q = (i & 63) * 4;
        *(float4*)&sm->bt[b][q] = *(const float4*)&buf[((size_t)b * Nn) * 256 + q];
    }
    if (tid == 0) {
        unsigned mb = smem_u32(&sm->mbar[0]);
        asm volatile("mbarrier.init.shared.b64 [%0], %1;" :: "r"(mb),   "r"(224) : "memory");
        asm volatile("mbarrier.init.shared.b64 [%0], %1;" :: "r"(mb+8), "r"(224) : "memory");
    }
    __syncthreads();

    if (tid < GPB) {
        const int g = tid;
        int p = 0, bp = 0;
        for (int t = 0; t < Tt; t++) {
            int trv = (sm->trbits[g][t >> 5] >> (t & 31)) & 1;
            int bi = (bp < Nn - 1) ? bp : (Nn - 1);
            sm->sch_bt[t][g] = (unsigned char)bi;
            int wp = trv ? ((p - 2 >= 0) ? p - 2 : 0) : p;
            if (wp > Nn - 1) wp = Nn - 1;
            sm->sch_wp[t][g] = (unsigned char)wp;
            sm->sch_rf[t][g] = (signed char)((trv && p >= 3) ? (p - 3) : -1);
            p  += trv ? -1 : 1;
            bp += trv ? 0 : 1;
        }
        sm->sch_bt[Tt][g] = sm->sch_bt[Tt - 1][g];
        int fin = (p - 1 >= 0) ? p - 1 : 0;
        sm->fin_ptr[g] = (fin > Nn - 1) ? Nn - 1 : fin;
    }
    __syncthreads();
    asm volatile("barrier.cluster.arrive.aligned;" ::: "memory");
    asm volatile("barrier.cluster.wait.aligned;"   ::: "memory");

    const unsigned hbar    = smem_u32(&sm->mbar[0]);
    const unsigned sbar    = hbar + 8;
    const unsigned hsbase  = smem_u32(&sm->h_s[0][0][0]);
    const unsigned redbase = smem_u32(&sm->red_s[0][0][0]);

    const int pb = tid >> 6;               // rename batch
    const int pd = (tid & 63) * 4;         // 4-float chunk
    // publisher mapping (tid in [128,352)): one warp per peer
    const int isPub = (tid >= 128 && tid < 352);
    const int pid   = (tid - 128) >> 5;
    const int peer  = pid + (pid >= r ? 1 : 0);
    const int plane = tid & 31;

    const float4 z4 = make_float4(0.f, 0.f, 0.f, 0.f);
    float4 rfa = z4;       // refill (loaded at t, consumed at t+1 rename)
    float4 bna = z4;       // next bt row (loaded at t, consumed at t P6)
    float loss_reg = 0.f;
    int sp = 0;
    int prevAny = 0;

    for (int t = 0; t < Tt; t++) {
        const int w5 = t >> 5, b5 = t & 31;
        const int rb = t & 1, wbuf = 1 - rb;

        unsigned anyr = 0;
#pragma unroll
        for (int g = 0; g < GPB; g++) anyr |= (sm->trbits[g][w5] >> b5) & 1u;

        // ---- P0: conditional sbar wait + reduce-rename (uses PREVIOUS rfa),
        //          then prefetch for next consumption ----
        if (prevAny) {
            wait_parity_cluster(sbar, sp & 1);
            const int slot = sp & 1;
            if ((sm->trbits[pb][(t - 1) >> 5] >> ((t - 1) & 31)) & 1) {
                float4 r0 = *(const float4*)&sm->red_s[slot][pb][pd];
                *(float4*)&sm->s1v[pb][pd] = r0;
                *(float4*)&sm->s2v[pb][pd] = rfa;
            }
            sp++;
        }
        {
            int nbt = sm->sch_bt[t + 1][pb];
            bna = __ldg((const float4*)&buf[((size_t)pb * Nn + nbt) * 256 + pd]);
            int rfi = sm->sch_rf[t][pb];   // note: rf[t] row == s2 needed at t+1
            rfa = (rfi >= 0)
                ? __ldcg((const float4*)&stck[((size_t)pb * Nn + rfi) * 256 + pd])
                : z4;
        }
        __syncthreads();   // SYNC0

        // ---- P1: tracker GEMM (k-split), kc3 waits hbar(t-1); lazy loss ----
        {
            const int col = tid & 63;
            const int kc  = (tid >> 6) & 3;
            const int kh  = tid >> 8;
            const int k0  = kh * 64;
            const float* xb; int xs;
            if (kc == 0)      { xb = &sm->bt[0][0];  xs = 256; }
            else if (kc == 1) { xb = &sm->s1v[0][0]; xs = 256; }
            else if (kc == 2) { xb = &sm->s2v[0][0]; xs = 256; }
            else {
                if (t > 0) wait_parity_cluster(hbar, (t - 1) & 1);
                xb = &sm->h_s[rb][0][0]; xs = 128;
            }
            const __half* wr = &sm->wTrk[(kc * 64 + col) * 130 + k0];
            float acc[GPB];
#pragma unroll
            for (int b = 0; b < GPB; b++) acc[b] = 0.f;
#pragma unroll 4
            for (int kl = 0; kl < 64; kl += 4) {
                float2 wf0 = __half22float2(*(const __half2*)&wr[kl]);
                float2 wf1 = __half22float2(*(const __half2*)&wr[kl + 2]);
#pragma unroll
                for (int b = 0; b < GPB; b++) {
                    float4 x = *(const float4*)&xb[b * xs + k0 + kl];
                    acc[b] += x.x * wf0.x + x.y * wf0.y + x.z * wf1.x + x.w * wf1.y;
                }
            }
            const int slot = (kc * 2 + kh) * 64 + col;
            *(float4*)&sm->pt[slot * 8]     = make_float4(acc[0], acc[1], acc[2], acc[3]);
            *(float4*)&sm->pt[slot * 8 + 4] = make_float4(acc[4], acc[5], acc[6], acc[7]);
        }
        if (t > 0 && tid >= 480) {        // lazy loss for t-1 (hbar(t-1) done: kc3)
            const int l = tid - 480;
            float p0 = 0.f, p1 = 0.f;
#pragma unroll
            for (int m = 0; m < 4; m++) {
                int j = l + 32 * m;
                float h = sm->h_s[rb][r][j];
                p0 += h * sm->wtrans[2 * j];
                p1 += h * sm->wtrans[2 * j + 1];
            }
#pragma unroll
            for (int off = 16; off > 0; off >>= 1) {
                p0 += __shfl_xor_sync(0xffffffffu, p0, off);
                p1 += __shfl_xor_sync(0xffffffffu, p1, off);
            }
            if (l == 0) {
                float l0 = p0 + sm->btr[0], l1 = p1 + sm->btr[1];
                float m = fmaxf(l0, l1);
                float lse = m + logf(expf(l0 - m) + expf(l1 - m));
                int trp = (sm->trbits[r][(t - 1) >> 5] >> ((t - 1) & 31)) & 1;
                loss_reg += lse - ((trp == 0) ? l0 : l1);
            }
        }
        __syncthreads();   // SYNC1

        // ---- P2: cell update (local h) ----
        if (tid < 128) {
            const int jj = tid >> 3, b = tid & 7;
            float ga[4];
#pragma unroll
            for (int g = 0; g < 4; g++) {
                int c = g * 16 + jj;
                float v = sm->pt[(c) * 8 + b]         + sm->pt[(64 + c) * 8 + b]
                        + sm->pt[(128 + c) * 8 + b]   + sm->pt[(192 + c) * 8 + b]
                        + sm->pt[(256 + c) * 8 + b]   + sm->pt[(320 + c) * 8 + b]
                        + sm->pt[(384 + c) * 8 + b]   + sm->pt[(448 + c) * 8 + b];
                if (t > 0) v += sm->bias_lat[c];
                ga[g] = v;
            }
            float cn = sigf(ga[2]) * sm->c_s[b][jj] + sigf(ga[1]) * tanhf(ga[0]);
            float hn = sigf(ga[3]) * tanhf(cn);
            sm->c_s[b][jj] = cn;
            sm->h_s[wbuf][b][(r << 4) + jj] = hn;
        }
        __syncthreads();   // SYNC2

        // ---- P3: h publish + arrive || tree (balanced, m2 waits hbar(t))
        //          || shift stack writes (warp 15) ----
        if (isPub) {
#pragma unroll
            for (int rr = 0; rr < 2; rr++) {
                int u = plane + rr * 32;
                int b = u >> 3, o = (u & 7) * 2;
                float2 hv = *(const float2*)&sm->h_s[wbuf][b][(r << 4) + o];
                unsigned la = hsbase + (unsigned)(((wbuf * GPB + b) * 128 + (r << 4) + o) * 4);
                st_remote_b64(la, peer, hv.x, hv.y);
            }
            arrive_peer_rel(hbar, peer);
        }
        if (anyr && tid < 480) {
            const int m   = tid / 160;            // 0=left(s2),1=right(s1),2=track(h)
            const int idx = tid - m * 160;
            const int kh  = (idx >= 80) ? 1 : 0;
            const int c   = idx - kh * 80;
            const int k0  = kh * 64;
            if (m == 2) wait_parity_cluster(hbar, t & 1);
            const float* xb = (m == 0) ? &sm->s2v[0][0]
                            : (m == 1) ? &sm->s1v[0][0] : &sm->h_s[wbuf][0][0];
            const int xs = (m == 2) ? 128 : 256;
            const __half* wr = &sm->wT[c * 386 + m * 128 + k0];
            float acc[GPB];
#pragma unroll
            for (int b = 0; b < GPB; b++) acc[b] = 0.f;
#pragma unroll 4
            for (int kl = 0; kl < 64; kl += 4) {
                float2 wf0 = __half22float2(*(const __half2*)&wr[kl]);
                float2 wf1 = __half22float2(*(const __half2*)&wr[kl + 2]);
#pragma unroll
                for (int b = 0; b < GPB; b++) {
                    float4 x = *(const float4*)&xb[b * xs + k0 + kl];
                    acc[b] += x.x * wf0.x + x.y * wf0.y + x.z * wf1.x + x.w * wf1.y;
                }
            }
            const int slot = (m * 2 + kh) * 80 + c;
            *(float4*)&sm->pt[slot * 8]     = make_float4(acc[0], acc[1], acc[2], acc[3]);
            *(float4*)&sm->pt[slot * 8 + 4] = make_float4(acc[4], acc[5], acc[6], acc[7]);
        }
        if (tid >= 480) {     // shift stack writes (bt stable until P6)
            const int u = tid - 480;
            const int b = u >> 2, q = (u & 3) * 8;
            if (((sm->trbits[b][w5] >> b5) & 1) == 0) {
                const int wp = sm->sch_wp[t][b];
                __stcg((float4*)&stck[((size_t)b * Nn + wp) * 256 + r * 32 + q],
                       *(const float4*)&sm->bt[b][r * 32 + q]);
                __stcg((float4*)&stck[((size_t)b * Nn + wp) * 256 + r * 32 + q + 4],
                       *(const float4*)&sm->bt[b][r * 32 + q + 4]);
            }
        }
        __syncthreads();   // SYNC3

        // ---- P4: compose (reduce batches) -> red_s local + stack stcg ----
        const int slotW = sp & 1;
        if (tid < 128) {
            const int jj = tid >> 3, b = tid & 7;
            if ((sm->trbits[b][w5] >> b5) & 1) {
                const int j = (r << 4) + jj;
                float gg[5];
#pragma unroll
                for (int g = 0; g < 5; g++) {
                    int c = g * 16 + jj;
                    gg[g] = sm->pt[c * 8 + b]          + sm->pt[(80 + c) * 8 + b]
                          + sm->pt[(160 + c) * 8 + b]  + sm->pt[(240 + c) * 8 + b]
                          + sm->pt[(320 + c) * 8 + b]  + sm->pt[(400 + c) * 8 + b]
                          + sm->bias_red[c];
                }
                float cn = tanhf(gg[0]) * sigf(gg[1])
                         + sigf(gg[2]) * sm->s2v[b][128 + j]
                         + sigf(gg[3]) * sm->s1v[b][128 + j];
                float v1 = cn;
                float v0 = sigf(gg[4]) * tanhf(cn);
                const int wp = sm->sch_wp[t][b];
                __stcg(&stck[((size_t)b * Nn + wp) * 256 + j], v0);
                __stcg(&stck[((size_t)b * Nn + wp) * 256 + 128 + j], v1);
                sm->red_s[slotW][b][j]       = v0;
                sm->red_s[slotW][b][128 + j] = v1;
            }
        }
        __syncthreads();   // SYNC4

        // ---- P5: red publish + sbar arrive (reduce only) + shift rename ----
        if (anyr && isPub) {
#pragma unroll
            for (int rr = 0; rr < 4; rr++) {
                int u = plane + rr * 32;                 // 0..127
                int half = u >> 6, b = (u >> 3) & 7, o = (u & 7) * 2;
                float2 rv = *(const float2*)&sm->red_s[slotW][b][half * 128 + (r << 4) + o];
                unsigned la = redbase + (unsigned)(((slotW * GPB + b) * 256
                               + half * 128 + (r << 4) + o) * 4);
                st_remote_b64(la, peer, rv.x, rv.y);
            }
            arrive_peer_rel(sbar, peer);
        }
        if (((sm->trbits[pb][w5] >> b5) & 1) == 0) {
            float4 s1a = *(const float4*)&sm->s1v[pb][pd];
            float4 bta = *(const float4*)&sm->bt[pb][pd];
            *(float4*)&sm->s2v[pb][pd] = s1a;
            *(float4*)&sm->s1v[pb][pd] = bta;
            *(float4*)&sm->bt[pb][pd]  = bna;
        }
        prevAny = anyr;
    }

    fence_cluster();
    asm volatile("barrier.cluster.arrive.aligned;" ::: "memory");
    asm volatile("barrier.cluster.wait.aligned;"   ::: "memory");

    // final step's loss
    if (tid >= 480) {
        const int l = tid - 480;
        const int wb_last = 1 - ((Tt - 1) & 1);
        float p0 = 0.f, p1 = 0.f;
#pragma unroll
        for (int m = 0; m < 4; m++) {
            int j = l + 32 * m;
            float h = sm->h_s[wb_last][r][j];
            p0 += h * sm->wtrans[2 * j];
            p1 += h * sm->wtrans[2 * j + 1];
        }
#pragma unroll
        for (int off = 16; off > 0; off >>= 1) {
            p0 += __shfl_xor_sync(0xffffffffu, p0, off);
            p1 += __shfl_xor_sync(0xffffffffu, p1, off);
        }
        if (l == 0) {
            float l0 = p0 + sm->btr[0], l1 = p1 + sm->btr[1];
            float m = fmaxf(l0, l1);
            float lse = m + logf(expf(l0 - m) + expf(l1 - m));
            int trp = (sm->trbits[r][(Tt - 1) >> 5] >> ((Tt - 1) & 31)) & 1;
            loss_reg += lse - ((trp == 0) ? l0 : l1);
            g_loss[b0 + r] = loss_reg;
        }
    }

    if (tid < 64) {
        int fin = sm->fin_ptr[r];
        float4 v = __ldcg((const float4*)&stck[((size_t)r * Nn + fin) * 256 + tid * 4]);
        *(float4*)&out_final[(size_t)(b0 + r) * 256 + tid * 4] = v;
    }
}

// ---------------------------------------------------------------------------
// Kernel 3: loss reduction
// ---------------------------------------------------------------------------
__global__ void loss_kernel(float* __restrict__ out, int loss_idx)
{
    __shared__ float sl[128];
    int tid = threadIdx.x;
    sl[tid] = g_loss[tid];
    __syncthreads();
    for (int off = 64; off > 0; off >>= 1) {
        if (tid < off) sl[tid] += sl[tid + off];
        __syncthreads();
    }
    if (tid == 0) out[loss_idx] = sl[0] / (float)(Tt * Bb);
}

// ---------------------------------------------------------------------------
extern "C" void kernel_launch(void* const* d_in, const int* in_sizes, int n_in,
                              void* d_out, int out_size)
{
    const int*   tokens      = (const int*)  d_in[0];
    const int*   transitions = (const int*)  d_in[1];
    const float* embed_table = (const float*)d_in[2];
    const float* W_proj      = (const float*)d_in[3];
    const float* W_buf       = (const float*)d_in[4];
    const float* W_s1        = (const float*)d_in[5];
    const float* W_s2        = (const float*)d_in[6];
    const float* W_lat       = (const float*)d_in[7];
    const float* b_lat       = (const float*)d_in[8];
    const float* W_trans     = (const float*)d_in[9];
    const float* b_trans     = (const float*)d_in[10];
    const float* W_left      = (const float*)d_in[11];
    const float* W_right     = (const float*)d_in[12];
    const float* W_track     = (const float*)d_in[13];
    const float* b_reduce    = (const float*)d_in[14];
    float* out = (float*)d_out;

    static bool attr_done = false;
    if (!attr_done) {
        cudaFuncSetAttribute(spinn_seq,
                             cudaFuncAttributeMaxDynamicSharedMemorySize,
                             (int)sizeof(Smem));
        attr_done = true;
    }

    embed_kernel<<<(Bb * Nn) / 16, 256>>>(tokens, embed_table, W_proj);
    spinn_seq<<<Bb, NT, sizeof(Smem)>>>(transitions,
                                        W_buf, W_s1, W_s2, W_lat, b_lat,
                                        W_trans, b_trans,
                                        W_left, W_right, W_track, b_reduce,
                                        out);
    loss_kernel<<<1, 128>>>(out, out_size - 1);
}

// round 11
// speedup vs baseline: 1.7651x; 1.5309x over previous
#include <cuda_runtime.h>
#include <cuda_fp16.h>
#include <math.h>

#define Bb 128
#define Nn 128
#define Ee 300
#define Tt 255
#define CSZ 8
#define GPB 8
#define NT 512

__device__ float g_buffer[Bb * Nn * 256];
__device__ float g_stack [Bb * Nn * 256];
__device__ float g_loss  [Bb];

__device__ __forceinline__ float sigf(float x) { return 1.0f / (1.0f + expf(-x)); }

__device__ __forceinline__ unsigned smem_u32(const void* p) {
    unsigned a;
    asm("{ .reg .u64 t; cvta.to.shared.u64 t, %1; cvt.u32.u64 %0, t; }" : "=r"(a) : "l"(p));
    return a;
}
__device__ __forceinline__ void fence_cluster() {
    asm volatile("fence.acq_rel.cluster;" ::: "memory");
}
__device__ __forceinline__ void arrive_peer_rel(unsigned la, int p) {
    asm volatile("{ .reg .b32 ra; mapa.shared::cluster.u32 ra, %0, %1;"
                 " mbarrier.arrive.release.cluster.shared::cluster.b64 _, [ra]; }"
                 :: "r"(la), "r"(p) : "memory");
}
__device__ __forceinline__ void wait_parity_cluster(unsigned a, unsigned par) {
    asm volatile("{ .reg .pred P;\n"
                 "W_%=:\n"
                 " mbarrier.try_wait.parity.acquire.cluster.shared::cta.b64 P, [%0], %1, 0x989680;\n"
                 " @P bra D_%=;\n"
                 " bra W_%=;\n"
                 "D_%=:\n}"
                 :: "r"(a), "r"(par) : "memory");
}
__device__ __forceinline__ void st_remote_b64(unsigned la, int p, float x, float y) {
    unsigned long long v = ((unsigned long long)__float_as_uint(y) << 32)
                         | (unsigned long long)__float_as_uint(x);
    asm volatile("{ .reg .b32 ra; mapa.shared::cluster.u32 ra, %0, %1;"
                 " st.shared::cluster.b64 [ra], %2; }"
                 :: "r"(la), "r"(p), "l"(v) : "memory");
}
__device__ __forceinline__ void ldmatrix_x4(unsigned& a0, unsigned& a1,
                                            unsigned& a2, unsigned& a3, unsigned addr) {
    asm volatile("ldmatrix.sync.aligned.m8n8.x4.shared.b16 {%0,%1,%2,%3}, [%4];"
                 : "=r"(a0), "=r"(a1), "=r"(a2), "=r"(a3) : "r"(addr));
}
__device__ __forceinline__ void mma16816(float& d0, float& d1, float& d2, float& d3,
                                         unsigned a0, unsigned a1, unsigned a2, unsigned a3,
                                         unsigned b0, unsigned b1) {
    asm volatile("mma.sync.aligned.m16n8k16.row.col.f32.f16.f16.f32 "
                 "{%0,%1,%2,%3}, {%4,%5,%6,%7}, {%8,%9}, {%0,%1,%2,%3};"
                 : "+f"(d0), "+f"(d1), "+f"(d2), "+f"(d3)
                 : "r"(a0), "r"(a1), "r"(a2), "r"(a3), "r"(b0), "r"(b1));
}
__device__ __forceinline__ unsigned pack_h2(float a, float b) {
    __half2 h = __floats2half2_rn(a, b);
    return *(unsigned*)&h;
}

// ---------------------------------------------------------------------------
// Kernel 1: buffer[b,n,:] = embed_table[tokens[b,n]] @ W_proj
// ---------------------------------------------------------------------------
__global__ void __launch_bounds__(256) embed_kernel(
    const int*   __restrict__ tokens,
    const float* __restrict__ embed_table,
    const float* __restrict__ W_proj)
{
    __shared__ float se[16 * Ee];
    __shared__ int   stok[16];
    const int blk = blockIdx.x;
    const int tid = threadIdx.x;

    if (tid < 16) stok[tid] = tokens[blk * 16 + tid];
    __syncthreads();
    for (int idx = tid; idx < 16 * Ee; idx += 256) {
        int j = idx / Ee, e = idx - j * Ee;
        se[idx] = embed_table[(size_t)stok[j] * Ee + e];
    }
    __syncthreads();

    const int col = tid;
    float acc[16];
#pragma unroll
    for (int j = 0; j < 16; j++) acc[j] = 0.0f;
    for (int e = 0; e < Ee; e++) {
        float w = W_proj[e * 256 + col];
#pragma unroll
        for (int j = 0; j < 16; j++) acc[j] += se[j * Ee + e] * w;
    }
#pragma unroll
    for (int j = 0; j < 16; j++)
        g_buffer[(size_t)(blk * 16 + j) * 256 + col] = acc[j];
}

// ---------------------------------------------------------------------------
// Kernel 2: clustered scan, tensor-core GEMMs (HMMA m16n8k16)
// ---------------------------------------------------------------------------
struct __align__(16) Smem {
    float h_s[2][GPB][128];
    float bt[GPB][256];
    float s1v[GPB][256];
    float s2v[GPB][256];
    float red_s[2][GPB][256];
    float pt[1664];                 // tracker 16*64 | tree (at 1024) 10*64
    float c_s[GPB][16];
    float bias_lat[64];
    float bias_red[80];
    float wtrans[256];
    float btr[2];
    int   fin_ptr[GPB];
    unsigned long long mbar[2];     // [0]=hbar, [1]=sbar (count 224)
    __align__(16) __half xh[16 * 520];   // fp16 activations [16 rows][bt|s1|s2|h]
    uint2 gbs[10 * 24 * 32];        // tree B fragments [warp][mm][lane]
    unsigned trbits[GPB][8];
    unsigned char sch_wp[Tt][GPB];
    unsigned char sch_bt[Tt + 1][GPB];
    signed char   sch_rf[Tt][GPB];
};

__global__ void __launch_bounds__(NT, 1) __cluster_dims__(CSZ, 1, 1)
spinn_seq(
    const int*   __restrict__ transitions,
    const float* __restrict__ W_buf,  const float* __restrict__ W_s1,
    const float* __restrict__ W_s2,   const float* __restrict__ W_lat,
    const float* __restrict__ b_lat,
    const float* __restrict__ W_trans,const float* __restrict__ b_trans,
    const float* __restrict__ W_left, const float* __restrict__ W_right,
    const float* __restrict__ W_track,const float* __restrict__ b_reduce,
    float* __restrict__ out_final)
{
    extern __shared__ char smraw[];
    Smem* sm = (Smem*)smraw;
    const int tid  = threadIdx.x;
    const int warp = tid >> 5;
    const int lane = tid & 31;
    const int r    = blockIdx.x & (CSZ - 1);
    const int b0   = blockIdx.x & ~(CSZ - 1);

    float*       stck = g_stack  + (size_t)b0 * Nn * 256;
    const float* buf  = g_buffer + (size_t)b0 * Nn * 256;

    // ---------------- init: B fragments ----------------
    unsigned tb0[16], tb1[16];          // tracker B frags, persistent regs
    {
        const int nt = warp & 7, kh = warp >> 3;
        const int cl = nt * 8 + (lane >> 2);
        const int G  = ((cl >> 4) << 7) + (r << 4) + (cl & 15);
#pragma unroll
        for (int mm = 0; mm < 16; mm++) {
            int kb = (kh * 16 + mm) * 16 + (lane & 3) * 2;
            float w00, w01, w10, w11;
            // global k -> source matrix
            {
                int k = kb;
                w00 = (k < 128) ? W_buf[k * 512 + G] : (k < 256) ? W_s1[(k - 128) * 512 + G]
                    : (k < 384) ? W_s2[(k - 256) * 512 + G] : W_lat[(k - 384) * 512 + G];
                k = kb + 1;
                w01 = (k < 128) ? W_buf[k * 512 + G] : (k < 256) ? W_s1[(k - 128) * 512 + G]
                    : (k < 384) ? W_s2[(k - 256) * 512 + G] : W_lat[(k - 384) * 512 + G];
                k = kb + 8;
                w10 = (k < 128) ? W_buf[k * 512 + G] : (k < 256) ? W_s1[(k - 128) * 512 + G]
                    : (k < 384) ? W_s2[(k - 256) * 512 + G] : W_lat[(k - 384) * 512 + G];
                k = kb + 9;
                w11 = (k < 128) ? W_buf[k * 512 + G] : (k < 256) ? W_s1[(k - 128) * 512 + G]
                    : (k < 384) ? W_s2[(k - 256) * 512 + G] : W_lat[(k - 384) * 512 + G];
            }
            tb0[mm] = pack_h2(w00, w01);
            tb1[mm] = pack_h2(w10, w11);
        }
    }
    if (warp < 10) {                     // tree B frags -> smem stash
        const int cl = warp * 8 + (lane >> 2);
        const int G  = ((cl >> 4) << 7) + (r << 4) + (cl & 15);
        for (int mm = 0; mm < 24; mm++) {
            int m  = mm >> 3;
            int kk = (mm & 7) * 16 + (lane & 3) * 2;
            const float* W = (m == 0) ? W_left : (m == 1) ? W_right : W_track;
            uint2 v;
            v.x = pack_h2(W[kk * 640 + G],       W[(kk + 1) * 640 + G]);
            v.y = pack_h2(W[(kk + 8) * 640 + G], W[(kk + 9) * 640 + G]);
            sm->gbs[(warp * 24 + mm) * 32 + lane] = v;
        }
    }
    if (tid < 64) sm->bias_lat[tid] = b_lat[((tid >> 4) << 7) + (r << 4) + (tid & 15)];
    if (tid < 80) sm->bias_red[tid] = b_reduce[((tid >> 4) << 7) + (r << 4) + (tid & 15)];
    if (tid < 256) sm->wtrans[tid] = W_trans[tid];
    if (tid < 2) sm->btr[tid] = b_trans[tid];
    if (tid < 64) {
        int g = tid >> 3, w = tid & 7;
        unsigned bits = 0;
        for (int i = 0; i < 32; i++) {
            int tt = w * 32 + i;
            if (tt < Tt) bits |= (unsigned)(transitions[(b0 + g) * Tt + tt] & 1) << i;
        }
        sm->trbits[g][w] = bits;
    }
    for (int i = tid; i < 2 * GPB * 128; i += NT) ((float*)sm->h_s)[i] = 0.f;
    for (int i = tid; i < GPB * 16;  i += NT) ((float*)sm->c_s)[i] = 0.f;
    for (int i = tid; i < GPB * 256; i += NT) {
        ((float*)sm->s1v)[i] = 0.f;
        ((float*)sm->s2v)[i] = 0.f;
    }
    for (int i = tid; i < 2 * GPB * 256; i += NT) ((float*)sm->red_s)[i] = 0.f;
    for (int i = tid; i < 16 * 520; i += NT) sm->xh[i] = __float2half(0.f);
    for (int i = tid; i < GPB * 64; i += NT) {
        int b = i >> 6, q = (i & 63) * 4;
        *(float4*)&sm->bt[b][q] = *(const float4*)&buf[((size_t)b * Nn) * 256 + q];
    }
    if (tid == 0) {
        unsigned mb = smem_u32(&sm->mbar[0]);
        asm volatile("mbarrier.init.shared.b64 [%0], %1;" :: "r"(mb),   "r"(224) : "memory");
        asm volatile("mbarrier.init.shared.b64 [%0], %1;" :: "r"(mb+8), "r"(224) : "memory");
    }
    __syncthreads();

    if (tid < GPB) {
        const int g = tid;
        int p = 0, bp = 0;
        for (int t = 0; t < Tt; t++) {
            int trv = (sm->trbits[g][t >> 5] >> (t & 31)) & 1;
            int bi = (bp < Nn - 1) ? bp : (Nn - 1);
            sm->sch_bt[t][g] = (unsigned char)bi;
            int wp = trv ? ((p - 2 >= 0) ? p - 2 : 0) : p;
            if (wp > Nn - 1) wp = Nn - 1;
            sm->sch_wp[t][g] = (unsigned char)wp;
            sm->sch_rf[t][g] = (signed char)((trv && p >= 3) ? (p - 3) : -1);
            p  += trv ? -1 : 1;
            bp += trv ? 0 : 1;
        }
        sm->sch_bt[Tt][g] = sm->sch_bt[Tt - 1][g];
        int fin = (p - 1 >= 0) ? p - 1 : 0;
        sm->fin_ptr[g] = (fin > Nn - 1) ? Nn - 1 : fin;
    }
    __syncthreads();
    asm volatile("barrier.cluster.arrive.aligned;" ::: "memory");
    asm volatile("barrier.cluster.wait.aligned;"   ::: "memory");

    const unsigned hbar    = smem_u32(&sm->mbar[0]);
    const unsigned sbar    = hbar + 8;
    const unsigned hsbase  = smem_u32(&sm->h_s[0][0][0]);
    const unsigned redbase = smem_u32(&sm->red_s[0][0][0]);
    const unsigned xhbase  = smem_u32(&sm->xh[0]);

    // ldmatrix lane addressing (A m16k16 row-major)
    const unsigned lrow  = lane & 15;
    const unsigned lcolb = (lane & 16) >> 1;            // 0 or 8
    const unsigned abase = xhbase + (lrow * 520u + lcolb) * 2u;

    const int pb = tid >> 6;               // rename batch
    const int pd = (tid & 63) * 4;         // 4-float chunk
    // publishers: warps 9..15 -> 7 peers
    const int isPub = (warp >= 9);
    const int pw    = warp - 9;
    const int peer  = pw + (pw >= r ? 1 : 0);

    const float4 z4 = make_float4(0.f, 0.f, 0.f, 0.f);
    float4 rfa = z4, bna = z4;
    float loss_reg = 0.f;
    int sp = 0;
    int prevAny = 0;

    for (int t = 0; t < Tt; t++) {
        const int w5 = t >> 5, b5 = t & 31;
        const int rb = t & 1, wbuf = 1 - rb;

        unsigned anyr = 0;
#pragma unroll
        for (int g = 0; g < GPB; g++) anyr |= (sm->trbits[g][w5] >> b5) & 1u;

        // ---- P0: conditional sbar wait + reduce-rename; prefetch ----
        if (prevAny) {
            wait_parity_cluster(sbar, sp & 1);
            const int slot = sp & 1;
            if ((sm->trbits[pb][(t - 1) >> 5] >> ((t - 1) & 31)) & 1) {
                float4 r0 = *(const float4*)&sm->red_s[slot][pb][pd];
                *(float4*)&sm->s1v[pb][pd] = r0;
                *(float4*)&sm->s2v[pb][pd] = rfa;
            }
            sp++;
        }
        {
            int nbt = sm->sch_bt[t + 1][pb];
            bna = __ldg((const float4*)&buf[((size_t)pb * Nn + nbt) * 256 + pd]);
            int rfi = sm->sch_rf[t][pb];
            rfa = (rfi >= 0)
                ? __ldcg((const float4*)&stck[((size_t)pb * Nn + rfi) * 256 + pd])
                : z4;
        }
        __syncthreads();   // SYNC0

        // ---- P1: xh fill cols 0..383 (bt|s1|s2) + lazy loss(t-1) ----
        {
            const int b = tid >> 6, seg = tid & 63;
            if (seg < 48) {
                const int col = seg * 8;
                const float* src = (col < 128) ? &sm->bt[b][col]
                                 : (col < 256) ? &sm->s1v[b][col - 128]
                                               : &sm->s2v[b][col - 256];
                float4 x0 = *(const float4*)src;
                float4 x1 = *(const float4*)(src + 4);
                uint4 v;
                v.x = pack_h2(x0.x, x0.y); v.y = pack_h2(x0.z, x0.w);
                v.z = pack_h2(x1.x, x1.y); v.w = pack_h2(x1.z, x1.w);
                *(uint4*)&sm->xh[b * 520 + col] = v;
            }
        }
        if (t > 0 && warp == 15) {         // loss for t-1 (h(t-1) synced at prev P5)
            float p0 = 0.f, p1 = 0.f;
#pragma unroll
            for (int m = 0; m < 4; m++) {
                int j = lane + 32 * m;
                float h = sm->h_s[rb][r][j];
                p0 += h * sm->wtrans[2 * j];
                p1 += h * sm->wtrans[2 * j + 1];
            }
#pragma unroll
            for (int off = 16; off > 0; off >>= 1) {
                p0 += __shfl_xor_sync(0xffffffffu, p0, off);
                p1 += __shfl_xor_sync(0xffffffffu, p1, off);
            }
            if (lane == 0) {
                float l0 = p0 + sm->btr[0], l1 = p1 + sm->btr[1];
                float m = fmaxf(l0, l1);
                float lse = m + logf(expf(l0 - m) + expf(l1 - m));
                int trp = (sm->trbits[r][(t - 1) >> 5] >> ((t - 1) & 31)) & 1;
                loss_reg += lse - ((trp == 0) ? l0 : l1);
            }
        }
        __syncthreads();   // SYNC1

        // ---- P2: tracker tensor-core GEMM (all 16 warps, 16 mma each) ----
        {
            float d0 = 0.f, d1 = 0.f, d2 = 0.f, d3 = 0.f;
#pragma unroll
            for (int mm = 0; mm < 16; mm++) {
                const unsigned k0 = ((unsigned)((warp >> 3) * 16 + mm)) * 16u;
                unsigned a0, a1, a2, a3;
                ldmatrix_x4(a0, a1, a2, a3, abase + k0 * 2u);
                mma16816(d0, d1, d2, d3, a0, a1, a2, a3, tb0[mm], tb1[mm]);
            }
            const int row = lane >> 2, cc = (lane & 3) * 2;
            sm->pt[warp * 64 + row * 8 + cc]     = d0;
            sm->pt[warp * 64 + row * 8 + cc + 1] = d1;
        }
        __syncthreads();   // SYNC2

        // ---- P3: cell update -> h_s[wbuf], c_s ----
        if (tid < 128) {
            const int jj = tid >> 3, b = tid & 7;
            float ga[4];
#pragma unroll
            for (int g = 0; g < 4; g++) {
                int c = g * 16 + jj;
                int u0 = (c >> 3), u1 = 8 + (c >> 3), o = b * 8 + (c & 7);
                float v = sm->pt[u0 * 64 + o] + sm->pt[u1 * 64 + o];
                if (t > 0) v += sm->bias_lat[c];
                ga[g] = v;
            }
            float cn = sigf(ga[2]) * sm->c_s[b][jj] + sigf(ga[1]) * tanhf(ga[0]);
            float hn = sigf(ga[3]) * tanhf(cn);
            sm->c_s[b][jj] = cn;
            sm->h_s[wbuf][b][(r << 4) + jj] = hn;
        }
        __syncthreads();   // SYNC3

        // ---- P4: h publish (warps 9-15) || tree m0,m1 mma (warps 0-9)
        //          || shift stack writes (warp 15 after publish) ----
        float e0 = 0.f, e1 = 0.f, e2 = 0.f, e3 = 0.f;
        if (isPub) {
#pragma unroll
            for (int rr = 0; rr < 2; rr++) {
                int u = lane + rr * 32;
                int b = u >> 3, o = (u & 7) * 2;
                float2 hv = *(const float2*)&sm->h_s[wbuf][b][(r << 4) + o];
                unsigned la = hsbase + (unsigned)(((wbuf * GPB + b) * 128 + (r << 4) + o) * 4);
                st_remote_b64(la, peer, hv.x, hv.y);
            }
            arrive_peer_rel(hbar, peer);
        }
        if (anyr && warp < 10) {
#pragma unroll
            for (int mm = 0; mm < 16; mm++) {
                const unsigned k0 = (unsigned)(((mm >> 3) ? 128 : 256) + (mm & 7) * 16);
                unsigned a0, a1, a2, a3;
                ldmatrix_x4(a0, a1, a2, a3, abase + k0 * 2u);
                uint2 bfr = sm->gbs[(warp * 24 + mm) * 32 + lane];
                mma16816(e0, e1, e2, e3, a0, a1, a2, a3, bfr.x, bfr.y);
            }
        }
        if (warp == 15) {  // shift stack writes (bt stable until rename)
            const int b = lane >> 2, q = (lane & 3) * 8;
            if (((sm->trbits[b][w5] >> b5) & 1) == 0) {
                const int wp = sm->sch_wp[t][b];
                __stcg((float4*)&stck[((size_t)b * Nn + wp) * 256 + r * 32 + q],
                       *(const float4*)&sm->bt[b][r * 32 + q]);
                __stcg((float4*)&stck[((size_t)b * Nn + wp) * 256 + r * 32 + q + 4],
                       *(const float4*)&sm->bt[b][r * 32 + q + 4]);
            }
        }

        // ---- P5: wait hbar(t) + fill xh h-cols (warps 10-15) ----
        if (warp >= 10) {
            wait_parity_cluster(hbar, t & 1);
            for (int i = tid - 320; i < 512; i += 192) {
                int b = i >> 6, o = (i & 63) * 2;
                __half2 hv = __floats2half2_rn(sm->h_s[wbuf][b][o], sm->h_s[wbuf][b][o + 1]);
                *(__half2*)&sm->xh[b * 520 + 384 + o] = hv;
            }
        }
        __syncthreads();   // SYNC4

        // ---- P5b: rename (shift batches; disjoint from reduce-batch readers) ----
        if (((sm->trbits[pb][w5] >> b5) & 1) == 0) {
            float4 s1a = *(const float4*)&sm->s1v[pb][pd];
            float4 bta = *(const float4*)&sm->bt[pb][pd];
            *(float4*)&sm->s2v[pb][pd] = s1a;
            *(float4*)&sm->s1v[pb][pd] = bta;
            *(float4*)&sm->bt[pb][pd]  = bna;
        }

        if (anyr) {
            // ---- P6: tree m2 (track, h(t)) + store frags ----
            if (warp < 10) {
#pragma unroll
                for (int mm = 16; mm < 24; mm++) {
                    const unsigned k0 = (unsigned)(384 + (mm & 7) * 16);
                    unsigned a0, a1, a2, a3;
                    ldmatrix_x4(a0, a1, a2, a3, abase + k0 * 2u);
                    uint2 bfr = sm->gbs[(warp * 24 + mm) * 32 + lane];
                    mma16816(e0, e1, e2, e3, a0, a1, a2, a3, bfr.x, bfr.y);
                }
                const int row = lane >> 2, cc = (lane & 3) * 2;
                sm->pt[1024 + warp * 64 + row * 8 + cc]     = e0;
                sm->pt[1024 + warp * 64 + row * 8 + cc + 1] = e1;
            }
            __syncthreads();   // SYNC5

            // ---- P7: compose -> red_s + stack stcg ----
            const int slotW = sp & 1;
            if (tid < 128) {
                const int jj = tid >> 3, b = tid & 7;
                if ((sm->trbits[b][w5] >> b5) & 1) {
                    const int j = (r << 4) + jj;
                    float gg[5];
#pragma unroll
                    for (int g = 0; g < 5; g++) {
                        int c = g * 16 + jj;
                        gg[g] = sm->pt[1024 + (c >> 3) * 64 + b * 8 + (c & 7)]
                              + sm->bias_red[c];
                    }
                    float cn = tanhf(gg[0]) * sigf(gg[1])
                             + sigf(gg[2]) * sm->s2v[b][128 + j]
                             + sigf(gg[3]) * sm->s1v[b][128 + j];
                    float v1 = cn;
                    float v0 = sigf(gg[4]) * tanhf(cn);
                    const int wp = sm->sch_wp[t][b];
                    __stcg(&stck[((size_t)b * Nn + wp) * 256 + j], v0);
                    __stcg(&stck[((size_t)b * Nn + wp) * 256 + 128 + j], v1);
                    sm->red_s[slotW][b][j]       = v0;
                    sm->red_s[slotW][b][128 + j] = v1;
                }
            }
            __syncthreads();   // SYNC6

            // ---- P8: red publish + sbar arrive ----
            if (isPub) {
#pragma unroll
                for (int rr = 0; rr < 4; rr++) {
                    int u = lane + rr * 32;
                    int half = u >> 6, b = (u >> 3) & 7, o = (u & 7) * 2;
                    float2 rv = *(const float2*)&sm->red_s[slotW][b][half * 128 + (r << 4) + o];
                    unsigned la = redbase + (unsigned)(((slotW * GPB + b) * 256
                                   + half * 128 + (r << 4) + o) * 4);
                    st_remote_b64(la, peer, rv.x, rv.y);
                }
                arrive_peer_rel(sbar, peer);
            }
        }
        prevAny = anyr;
    }

    fence_cluster();
    asm volatile("barrier.cluster.arrive.aligned;" ::: "memory");
    asm volatile("barrier.cluster.wait.aligned;"   ::: "memory");

    // final step's loss
    if (warp == 15) {
        const int wb_last = 1 - ((Tt - 1) & 1);
        float p0 = 0.f, p1 = 0.f;
#pragma unroll
        for (int m = 0; m < 4; m++) {
            int j = lane + 32 * m;
            float h = sm->h_s[wb_last][r][j];
            p0 += h * sm->wtrans[2 * j];
            p1 += h * sm->wtrans[2 * j + 1];
        }
#pragma unroll
        for (int off = 16; off > 0; off >>= 1) {
            p0 += __shfl_xor_sync(0xffffffffu, p0, off);
            p1 += __shfl_xor_sync(0xffffffffu, p1, off);
        }
        if (lane == 0) {
            float l0 = p0 + sm->btr[0], l1 = p1 + sm->btr[1];
            float m = fmaxf(l0, l1);
            float lse = m + logf(expf(l0 - m) + expf(l1 - m));
            int trp = (sm->trbits[r][(Tt - 1) >> 5] >> ((Tt - 1) & 31)) & 1;
            loss_reg += lse - ((trp == 0) ? l0 : l1);
            g_loss[b0 + r] = loss_reg;
        }
    }

    if (tid < 64) {
        int fin = sm->fin_ptr[r];
        float4 v = __ldcg((const float4*)&stck[((size_t)r * Nn + fin) * 256 + tid * 4]);
        *(float4*)&out_final[(size_t)(b0 + r) * 256 + tid * 4] = v;
    }
}

// ---------------------------------------------------------------------------
// Kernel 3: loss reduction
// ---------------------------------------------------------------------------
__global__ void loss_kernel(float* __restrict__ out, int loss_idx)
{
    __shared__ float sl[128];
    int tid = threadIdx.x;
    sl[tid] = g_loss[tid];
    __syncthreads();
    for (int off = 64; off > 0; off >>= 1) {
        if (tid < off) sl[tid] += sl[tid + off];
        __syncthreads();
    }
    if (tid == 0) out[loss_idx] = sl[0] / (float)(Tt * Bb);
}

// ---------------------------------------------------------------------------
extern "C" void kernel_launch(void* const* d_in, const int* in_sizes, int n_in,
                              void* d_out, int out_size)
{
    const int*   tokens      = (const int*)  d_in[0];
    const int*   transitions = (const int*)  d_in[1];
    const float* embed_table = (const float*)d_in[2];
    const float* W_proj      = (const float*)d_in[3];
    const float* W_buf       = (const float*)d_in[4];
    const float* W_s1        = (const float*)d_in[5];
    const float* W_s2        = (const float*)d_in[6];
    const float* W_lat       = (const float*)d_in[7];
    const float* b_lat       = (const float*)d_in[8];
    const float* W_trans     = (const float*)d_in[9];
    const float* b_trans     = (const float*)d_in[10];
    const float* W_left      = (const float*)d_in[11];
    const float* W_right     = (const float*)d_in[12];
    const float* W_track     = (const float*)d_in[13];
    const float* b_reduce    = (const float*)d_in[14];
    float* out = (float*)d_out;

    static bool attr_done = false;
    if (!attr_done) {
        cudaFuncSetAttribute(spinn_seq,
                             cudaFuncAttributeMaxDynamicSharedMemorySize,
                             (int)sizeof(Smem));
        attr_done = true;
    }

    embed_kernel<<<(Bb * Nn) / 16, 256>>>(tokens, embed_table, W_proj);
    spinn_seq<<<Bb, NT, sizeof(Smem)>>>(transitions,
                                        W_buf, W_s1, W_s2, W_lat, b_lat,
                                        W_trans, b_trans,
                                        W_left, W_right, W_track, b_reduce,
                                        out);
    loss_kernel<<<1, 128>>>(out, out_size - 1);
}